// round 16
// baseline (speedup 1.0000x reference)
#include <cuda_runtime.h>
#include <cuda_fp16.h>
#include <mma.h>
#include <cstdint>

using namespace nvcuda;

#define NB 32768
#define NC 1024
#define NCH 256
#define NR 16

// ---------------- device scratch ----------------
__device__ __half g_h1[(size_t)NB * NCH];
__device__ __half g_Wcat[NC * 2 * NCH];
__device__ __half g_W1b[NCH * NCH];
__device__ __half g_Wbig[NCH * NC];
__device__ float g_T1[NCH * NR];
__device__ float g_Wueff[NCH * NC];
__device__ float g_Wf1[NCH * NCH];
__device__ float g_Wf2[NCH * NCH];
__device__ float g_v2[NCH];
__device__ float g_bu1[NR];
__device__ float g_bueff[NC];
__device__ float g_bbig[NC];

// ---------------- cp.async helpers ----------------
__device__ __forceinline__ void cp16(void* s, const void* g) {
    unsigned int sa = (unsigned int)__cvta_generic_to_shared(s);
    asm volatile("cp.async.cg.shared.global [%0], [%1], 16;\n" :: "r"(sa), "l"(g));
}
__device__ __forceinline__ void cp_commit() { asm volatile("cp.async.commit_group;\n" ::: "memory"); }
template<int N>
__device__ __forceinline__ void cp_wait() { asm volatile("cp.async.wait_group %0;\n" :: "n"(N) : "memory"); }

// ---------------- fp32 fold GEMM tile (k-step 32), f32 or f16 output ----------------
template <typename OutT>
__device__ void gemm_tile32(const float* __restrict__ A, const float* __restrict__ B,
                            OutT* __restrict__ C, int N, int K, int m0, int n0,
                            int tid, char* sm) {
    float (*As)[33] = (float(*)[33])sm;
    float (*Bs)[64] = (float(*)[64])(sm + 64 * 33 * 4);
    int ty = tid >> 4, tx = tid & 15;
    float acc[4][4] = {};
    for (int k0 = 0; k0 < K; k0 += 32) {
        #pragma unroll
        for (int l = 0; l < 8; l++) {
            int idx = tid + l * 256;
            int r = idx >> 5, c = idx & 31;
            As[r][c] = A[(size_t)(m0 + r) * K + k0 + c];
        }
        #pragma unroll
        for (int l = 0; l < 8; l++) {
            int idx = tid + l * 256;
            int r = idx >> 6, c = idx & 63;
            Bs[r][c] = B[(size_t)(k0 + r) * N + n0 + c];
        }
        __syncthreads();
        #pragma unroll
        for (int k = 0; k < 32; k++) {
            float a[4], b[4];
            #pragma unroll
            for (int i = 0; i < 4; i++) a[i] = As[ty * 4 + i][k];
            #pragma unroll
            for (int j = 0; j < 4; j++) b[j] = Bs[k][tx * 4 + j];
            #pragma unroll
            for (int i = 0; i < 4; i++)
                #pragma unroll
                for (int j = 0; j < 4; j++) acc[i][j] += a[i] * b[j];
        }
        __syncthreads();
    }
    #pragma unroll
    for (int i = 0; i < 4; i++)
        #pragma unroll
        for (int j = 0; j < 4; j++)
            C[(size_t)(m0 + ty * 4 + i) * N + n0 + tx * 4 + j] = (OutT)acc[i][j];
}

// ---------------- prologue kernels ----------------

__global__ void k_convWcat(const float* __restrict__ Wd, const float* __restrict__ dww,
                           const float* __restrict__ Wg) {
    int idx = blockIdx.x * 256 + threadIdx.x;
    int k = idx >> 9, j = idx & 511;
    float v = (j < NCH) ? Wd[k * NCH + j] * dww[j] : Wg[k * NCH + (j - NCH)];
    g_Wcat[idx] = __float2half(v);
}

__global__ void k_fold(const float* __restrict__ Wu, const float* __restrict__ Wld,
                       const float* __restrict__ bu, const float* __restrict__ W1) {
    int b = blockIdx.x, tid = threadIdx.x;
    if (b >= 257) {
        int idx = (b - 257) * 256 + tid;
        g_W1b[idx] = __float2half(W1[idx]);
        return;
    }
    int wid = tid >> 5, lane = tid & 31;
    if (b == 256) {
        if (tid < NR) {
            float s = 0.f;
            for (int c = 0; c < NC; c++) s += bu[c] * Wld[c * NR + tid];
            g_bu1[tid] = s;
        }
        return;
    }
    float acc[NR];
    #pragma unroll
    for (int r = 0; r < NR; r++) acc[r] = 0.f;
    for (int c = tid; c < NC; c += 256) {
        float w = Wu[b * NC + c];
        #pragma unroll
        for (int r = 0; r < NR; r++) acc[r] += w * Wld[c * NR + r];
    }
    #pragma unroll
    for (int r = 0; r < NR; r++)
        #pragma unroll
        for (int o = 16; o > 0; o >>= 1) acc[r] += __shfl_xor_sync(0xffffffffu, acc[r], o);
    __shared__ float s[8][NR];
    if (lane == 0)
        #pragma unroll
        for (int r = 0; r < NR; r++) s[wid][r] = acc[r];
    __syncthreads();
    if (tid < NR) {
        float v = 0.f;
        #pragma unroll
        for (int w = 0; w < 8; w++) v += s[w][tid];
        g_T1[b * NR + tid] = v;
    }
}

__global__ void k_pre1(const float* __restrict__ Wu, const float* __restrict__ Wlu,
                       const float* __restrict__ bu, const float* __restrict__ W2,
                       const float* __restrict__ Wv, const float* __restrict__ b2,
                       const float* __restrict__ bv, const float* __restrict__ Wo,
                       const float* __restrict__ bo) {
    __shared__ char sm[16896];
    int b = blockIdx.x, tid = threadIdx.x;
    if (b < 1024) {
        int idx = b * 256 + tid;
        int i = idx >> 10, c = idx & 1023;
        float s = Wu[idx];
        #pragma unroll
        for (int r = 0; r < NR; r++) s += g_T1[i * NR + r] * Wlu[r * NC + c];
        g_Wueff[idx] = s;
        return;
    }
    if (b < 1028) {
        int c = (b - 1024) * 256 + tid;
        float s = bu[c];
        #pragma unroll
        for (int r = 0; r < NR; r++) s += g_bu1[r] * Wlu[r * NC + c];
        g_bueff[c] = s;
        return;
    }
    if (b < 1044) {
        int t = b - 1028;
        gemm_tile32<float>(W2, Wv, g_Wf1, NCH, NCH, (t >> 2) * 64, (t & 3) * 64, tid, sm);
        return;
    }
    float* sv1 = (float*)sm;
    int n = tid;
    float s = bv[n];
    for (int k = 0; k < NCH; k++) s += b2[k] * Wv[k * NCH + n];
    sv1[n] = s;
    __syncthreads();
    float t = bo[n];
    for (int k = 0; k < NCH; k++) t += sv1[k] * Wo[k * NCH + n];
    g_v2[n] = t;
}

__global__ void k_pre2(const float* __restrict__ Wo) {
    __shared__ char sm[16896];
    int t = blockIdx.x;
    gemm_tile32<float>(g_Wf1, Wo, g_Wf2, NCH, NCH, (t >> 2) * 64, (t & 3) * 64, threadIdx.x, sm);
}

__global__ void k_pre3() {
    __shared__ char sm[16896];
    int b = blockIdx.x, tid = threadIdx.x;
    if (b < 64) {
        gemm_tile32<__half>(g_Wf2, g_Wueff, g_Wbig, NC, NCH, (b >> 4) * 64, (b & 15) * 64, tid, sm);
        return;
    }
    int n = (b - 64) * 256 + tid;
    float s = g_bueff[n];
    for (int k = 0; k < NCH; k++) s += g_v2[k] * g_Wueff[k * NC + n];
    g_bbig[n] = s;
}

// ---------------- fused LN + GLU GEMM (R14-proven, fp16; mbase grid offset) ----------------
#define GLU_SAS 1032
#define GLU_SBS 520
#define GLU_PS  520
#define GLU_ASZ (64 * GLU_SAS * 2)
#define GLU_BSZ (32 * GLU_SBS * 2)
#define GLU_SMEM (GLU_ASZ + 3 * GLU_BSZ)

__device__ __forceinline__ void glu_prefB(__half* sB, int k0, int tid) {
    #pragma unroll
    for (int j = 0; j < 8; j++) {
        int idx = tid + j * 256;
        int row = idx >> 6, c16 = idx & 63;
        cp16(sB + row * GLU_SBS + c16 * 8, g_Wcat + (size_t)(k0 + row) * 512 + c16 * 8);
    }
}

__global__ __launch_bounds__(256, 1)
void k_glu(const float* __restrict__ x, const float* __restrict__ lg,
           const float* __restrict__ lb, const float* __restrict__ bd,
           const float* __restrict__ dww, const float* __restrict__ bg,
           const float* __restrict__ dwb, int mbase) {
    extern __shared__ char smem[];
    __half* sA = (__half*)smem;
    __half* sB[3] = {
        (__half*)(smem + GLU_ASZ),
        (__half*)(smem + GLU_ASZ + GLU_BSZ),
        (__half*)(smem + GLU_ASZ + 2 * GLU_BSZ)
    };
    __half* patch = (__half*)smem;

    const int tid = threadIdx.x, wid = tid >> 5, lane = tid & 31;
    const int m0 = (blockIdx.x + mbase) * 64;

    glu_prefB(sB[0], 0, tid);
    cp_commit();

    #pragma unroll
    for (int rr = 0; rr < 8; rr++) {
        int r = wid * 8 + rr;
        const float4* xr = (const float4*)(x + (size_t)(m0 + r) * NC);
        float4 v[8];
        float s = 0.f, q = 0.f;
        #pragma unroll
        for (int i = 0; i < 8; i++) {
            v[i] = xr[lane + i * 32];
            s += v[i].x + v[i].y + v[i].z + v[i].w;
            q = fmaf(v[i].x, v[i].x, q); q = fmaf(v[i].y, v[i].y, q);
            q = fmaf(v[i].z, v[i].z, q); q = fmaf(v[i].w, v[i].w, q);
        }
        #pragma unroll
        for (int o = 16; o > 0; o >>= 1) {
            s += __shfl_xor_sync(0xffffffffu, s, o);
            q += __shfl_xor_sync(0xffffffffu, q, o);
        }
        float mean = s * (1.f / NC);
        float rstd = rsqrtf(q * (1.f / NC) - mean * mean + 1e-5f);
        #pragma unroll
        for (int i = 0; i < 8; i++) {
            float4 g4 = ((const float4*)lg)[lane + i * 32];
            float4 b4 = ((const float4*)lb)[lane + i * 32];
            __align__(8) __half o4[4];
            o4[0] = __float2half((v[i].x - mean) * rstd * g4.x + b4.x);
            o4[1] = __float2half((v[i].y - mean) * rstd * g4.y + b4.y);
            o4[2] = __float2half((v[i].z - mean) * rstd * g4.z + b4.z);
            o4[3] = __float2half((v[i].w - mean) * rstd * g4.w + b4.w);
            *(uint2*)(sA + r * GLU_SAS + (lane + i * 32) * 4) = *(const uint2*)o4;
        }
    }
    glu_prefB(sB[1], 32, tid);
    cp_commit();
    cp_wait<1>();
    __syncthreads();

    const int wm = wid >> 2, wn = wid & 3;
    wmma::fragment<wmma::accumulator, 16, 16, 16, __half> acc[2][8];
    #pragma unroll
    for (int i = 0; i < 2; i++)
        #pragma unroll
        for (int j = 0; j < 8; j++) wmma::fill_fragment(acc[i][j], __float2half(0.f));

    for (int it = 0; it < 32; it++) {
        int k0 = it * 32;
        if (it + 2 < 32) { glu_prefB(sB[(it + 2) % 3], k0 + 64, tid); cp_commit(); }
        __half* sBc = sB[it % 3];
        #pragma unroll
        for (int kk = 0; kk < 32; kk += 16) {
            wmma::fragment<wmma::matrix_a, 16, 16, 16, __half, wmma::row_major> af[2];
            #pragma unroll
            for (int i = 0; i < 2; i++)
                wmma::load_matrix_sync(af[i], sA + (wm * 32 + i * 16) * GLU_SAS + k0 + kk, GLU_SAS);
            #pragma unroll
            for (int gset = 0; gset < 2; gset++) {
                wmma::fragment<wmma::matrix_b, 16, 16, 16, __half, wmma::row_major> bf[4];
                #pragma unroll
                for (int j = 0; j < 4; j++)
                    wmma::load_matrix_sync(bf[j], sBc + kk * GLU_SBS + wn * 128 + gset * 64 + j * 16, GLU_SBS);
                #pragma unroll
                for (int i = 0; i < 2; i++)
                    #pragma unroll
                    for (int j = 0; j < 4; j++)
                        wmma::mma_sync(acc[i][gset * 4 + j], af[i], bf[j], acc[i][gset * 4 + j]);
            }
        }
        if (it < 31) {
            if (it < 30) cp_wait<1>();
            else         cp_wait<0>();
            __syncthreads();
        }
    }
    __syncthreads();

    #pragma unroll
    for (int i = 0; i < 2; i++)
        #pragma unroll
        for (int j = 0; j < 8; j++)
            wmma::store_matrix_sync(patch + (size_t)(wm * 32 + i * 16) * GLU_PS + wn * 128 + j * 16,
                                    acc[i][j], GLU_PS, wmma::mem_row_major);
    __syncthreads();

    const int r = tid >> 2;
    const int cb = (tid & 3) * 64;
    #pragma unroll
    for (int c8 = 0; c8 < 64; c8 += 8) {
        __align__(16) __half tmp[8];
        #pragma unroll
        for (int t = 0; t < 8; t++) {
            int j = cb + c8 + t;
            float a = __half2float(patch[r * GLU_PS + j]) + bd[j] * dww[j];
            float g = __half2float(patch[r * GLU_PS + 256 + j]) + bg[j];
            float sg = 1.f / (1.f + __expf(-g));
            tmp[t] = __float2half(a * sg + dwb[j]);
        }
        *(uint4*)(g_h1 + (size_t)(m0 + r) * NCH + cb + c8) = *(const uint4*)tmp;
    }
}

// ---------------- k_tail v3 (R14-proven, fp16; mbase grid offset) ----------------
#define T3_HS 264
#define T3_W1S 264
#define T3_W2S 520
#define T3_PS 260
#define T3_OFF_RING 33792
#define T3_BUF 33280
#define T3_OFF_PATCH 133632
#define T3_SMEM 200192

__device__ __forceinline__ float gelu_tanh(float v) {
    return 0.5f * v * (1.f + tanhf(0.7978845608028654f * (v + 0.044715f * v * v * v)));
}

__device__ __forceinline__ void t3_prefW(char* smem, int t, int tid) {
    __half* dst = (__half*)(smem + T3_OFF_RING + (t % 3) * T3_BUF);
    if (t < 8) {
        int k0 = t * 32;
        #pragma unroll
        for (int j = 0; j < 4; j++) {
            int idx = tid + j * 256;
            int row = idx >> 5, c16 = idx & 31;
            cp16(dst + row * T3_W1S + c16 * 8, g_W1b + (size_t)(k0 + row) * NCH + c16 * 8);
        }
    } else {
        int np = (t - 8) >> 3, k0 = ((t - 8) & 7) * 32;
        #pragma unroll
        for (int j = 0; j < 8; j++) {
            int idx = tid + j * 256;
            int row = idx >> 6, c16 = idx & 63;
            cp16(dst + row * T3_W2S + c16 * 8, g_Wbig + (size_t)(k0 + row) * NC + np * 512 + c16 * 8);
        }
    }
}

__global__ __launch_bounds__(256, 1)
void k_tail(const float* __restrict__ b1, const float* __restrict__ x,
            float* __restrict__ out, int mbase) {
    extern __shared__ char smem[];
    __half* sU = (__half*)smem;
    __half* patch = (__half*)(smem + T3_OFF_PATCH);

    const int tid = threadIdx.x, wid = tid >> 5;
    const int wm = wid >> 2, wn = wid & 3;
    const int m0 = (blockIdx.x + mbase) * 64;

    #pragma unroll
    for (int j = 0; j < 8; j++) {
        int idx = tid + j * 256;
        int row = idx >> 5, c16 = idx & 31;
        cp16(sU + row * T3_HS + c16 * 8, g_h1 + (size_t)(m0 + row) * NCH + c16 * 8);
    }
    cp_commit();
    t3_prefW(smem, 0, tid); cp_commit();
    t3_prefW(smem, 1, tid); cp_commit();

    wmma::fragment<wmma::accumulator, 16, 16, 16, __half> acc[2][8];
    #pragma unroll
    for (int i = 0; i < 2; i++)
        #pragma unroll
        for (int j = 0; j < 8; j++) wmma::fill_fragment(acc[i][j], __float2half(0.f));

    for (int t = 0; t < 24; t++) {
        if (t < 23) cp_wait<1>(); else cp_wait<0>();
        __syncthreads();
        __half* sW = (__half*)(smem + T3_OFF_RING + (t % 3) * T3_BUF);

        if (t < 8) {
            int k0 = t * 32;
            #pragma unroll
            for (int kk = 0; kk < 32; kk += 16) {
                wmma::fragment<wmma::matrix_a, 16, 16, 16, __half, wmma::row_major> af[2];
                wmma::fragment<wmma::matrix_b, 16, 16, 16, __half, wmma::row_major> bf[4];
                #pragma unroll
                for (int i = 0; i < 2; i++)
                    wmma::load_matrix_sync(af[i], sU + (wm * 32 + i * 16) * T3_HS + k0 + kk, T3_HS);
                #pragma unroll
                for (int j = 0; j < 4; j++)
                    wmma::load_matrix_sync(bf[j], sW + kk * T3_W1S + wn * 64 + j * 16, T3_W1S);
                #pragma unroll
                for (int i = 0; i < 2; i++)
                    #pragma unroll
                    for (int j = 0; j < 4; j++)
                        wmma::mma_sync(acc[i][j], af[i], bf[j], acc[i][j]);
            }
        } else {
            int k0 = ((t - 8) & 7) * 32;
            #pragma unroll
            for (int kk = 0; kk < 32; kk += 16) {
                wmma::fragment<wmma::matrix_a, 16, 16, 16, __half, wmma::row_major> af[2];
                #pragma unroll
                for (int i = 0; i < 2; i++)
                    wmma::load_matrix_sync(af[i], sU + (wm * 32 + i * 16) * T3_HS + k0 + kk, T3_HS);
                #pragma unroll
                for (int gset = 0; gset < 2; gset++) {
                    wmma::fragment<wmma::matrix_b, 16, 16, 16, __half, wmma::row_major> bf[4];
                    #pragma unroll
                    for (int j = 0; j < 4; j++)
                        wmma::load_matrix_sync(bf[j], sW + kk * T3_W2S + wn * 128 + gset * 64 + j * 16, T3_W2S);
                    #pragma unroll
                    for (int i = 0; i < 2; i++)
                        #pragma unroll
                        for (int j = 0; j < 4; j++)
                            wmma::mma_sync(acc[i][gset * 4 + j], af[i], bf[j], acc[i][gset * 4 + j]);
                }
            }
        }
        __syncthreads();
        if (t + 2 < 24) { t3_prefW(smem, t + 2, tid); cp_commit(); }

        if (t == 7) {
            #pragma unroll
            for (int i = 0; i < 2; i++)
                #pragma unroll
                for (int j = 0; j < 4; j++)
                    wmma::store_matrix_sync(patch + (size_t)(wm * 32 + i * 16) * T3_PS + wn * 64 + j * 16,
                                            acc[i][j], T3_PS, wmma::mem_row_major);
            __syncthreads();
            const int r = tid >> 2, cb = (tid & 3) * 64;
            #pragma unroll
            for (int c8 = 0; c8 < 64; c8 += 8) {
                __align__(16) __half tmp[8];
                #pragma unroll
                for (int u = 0; u < 8; u++) {
                    int j = cb + c8 + u;
                    tmp[u] = __float2half(gelu_tanh(__half2float(patch[r * T3_PS + j]) + b1[j]));
                }
                *(uint4*)(sU + r * T3_HS + cb + c8) = *(const uint4*)tmp;
            }
            __syncthreads();
            #pragma unroll
            for (int i = 0; i < 2; i++)
                #pragma unroll
                for (int j = 0; j < 8; j++) wmma::fill_fragment(acc[i][j], __float2half(0.f));
        } else if (t == 15 || t == 23) {
            int np = (t - 8) >> 3;
            #pragma unroll
            for (int half = 0; half < 2; half++) {
                if ((wn >> 1) == half) {
                    #pragma unroll
                    for (int i = 0; i < 2; i++)
                        #pragma unroll
                        for (int j = 0; j < 8; j++)
                            wmma::store_matrix_sync(patch + (size_t)(wm * 32 + i * 16) * T3_PS
                                                        + (wn & 1) * 128 + j * 16,
                                                    acc[i][j], T3_PS, wmma::mem_row_major);
                }
                __syncthreads();
                const int r = tid >> 2, cb = (tid & 3) * 64;
                const int gr = m0 + r;
                #pragma unroll
                for (int c4 = 0; c4 < 64; c4 += 4) {
                    int j = cb + c4;
                    int gc = np * 512 + half * 256 + j;
                    float4 xo = *(const float4*)(x + (size_t)gr * NC + gc);
                    float4 o;
                    o.x = 0.5f * (__half2float(patch[r * T3_PS + j + 0]) + g_bbig[gc + 0]) + 0.5f * xo.x;
                    o.y = 0.5f * (__half2float(patch[r * T3_PS + j + 1]) + g_bbig[gc + 1]) + 0.5f * xo.y;
                    o.z = 0.5f * (__half2float(patch[r * T3_PS + j + 2]) + g_bbig[gc + 2]) + 0.5f * xo.z;
                    o.w = 0.5f * (__half2float(patch[r * T3_PS + j + 3]) + g_bbig[gc + 3]) + 0.5f * xo.w;
                    *(float4*)(out + (size_t)gr * NC + gc) = o;
                }
                __syncthreads();
            }
            if (t == 15) {
                #pragma unroll
                for (int i = 0; i < 2; i++)
                    #pragma unroll
                    for (int j = 0; j < 8; j++) wmma::fill_fragment(acc[i][j], __float2half(0.f));
            }
        }
    }
}

// ---------------- host launch: 3-stream pipelined fork/join ----------------
extern "C" void kernel_launch(void* const* d_in, const int* in_sizes, int n_in,
                              void* d_out, int out_size) {
    const float* x   = (const float*)d_in[0];
    const float* lng = (const float*)d_in[1];
    const float* lnb = (const float*)d_in[2];
    const float* Wd  = (const float*)d_in[3];
    const float* bd  = (const float*)d_in[4];
    const float* Wg  = (const float*)d_in[5];
    const float* bg  = (const float*)d_in[6];
    const float* dww = (const float*)d_in[7];
    const float* dwb = (const float*)d_in[8];
    const float* W1  = (const float*)d_in[9];
    const float* b1  = (const float*)d_in[10];
    const float* W2  = (const float*)d_in[11];
    const float* b2  = (const float*)d_in[12];
    // d_in[13..16] dead (softmax over one key == 1)
    const float* Wv  = (const float*)d_in[17];
    const float* bv  = (const float*)d_in[18];
    const float* Wo  = (const float*)d_in[19];
    const float* bo  = (const float*)d_in[20];
    const float* Wu  = (const float*)d_in[21];
    const float* bu  = (const float*)d_in[22];
    const float* Wld = (const float*)d_in[23];
    const float* Wlu = (const float*)d_in[24];
    float* out = (float*)d_out;

    static int inited = 0;
    static cudaStream_t s2, s3;
    static cudaEvent_t evStart, evPre, evG0, evT0;
    if (!inited) {
        cudaFuncSetAttribute(k_glu,  cudaFuncAttributeMaxDynamicSharedMemorySize, GLU_SMEM);
        cudaFuncSetAttribute(k_tail, cudaFuncAttributeMaxDynamicSharedMemorySize, T3_SMEM);
        cudaStreamCreateWithFlags(&s2, cudaStreamNonBlocking);
        cudaStreamCreateWithFlags(&s3, cudaStreamNonBlocking);
        cudaEventCreateWithFlags(&evStart, cudaEventDisableTiming);
        cudaEventCreateWithFlags(&evPre, cudaEventDisableTiming);
        cudaEventCreateWithFlags(&evG0, cudaEventDisableTiming);
        cudaEventCreateWithFlags(&evT0, cudaEventDisableTiming);
        inited = 1;
    }

    cudaEventRecord(evStart, 0);
    cudaStreamWaitEvent(s2, evStart, 0);

    // side stream s2: weight folding chain
    k_fold<<<513, 256, 0, s2>>>(Wu, Wld, bu, W1);
    k_pre1<<<1045, 256, 0, s2>>>(Wu, Wlu, bu, W2, Wv, b2, bv, Wo, bo);
    k_pre2<<<16, 256, 0, s2>>>(Wo);
    k_pre3<<<68, 256, 0, s2>>>();
    cudaEventRecord(evPre, s2);

    // main stream: conv + glu half 0
    k_convWcat<<<2048, 256>>>(Wd, dww, Wg);
    k_glu<<<256, 256, GLU_SMEM>>>(x, lng, lnb, bd, dww, bg, dwb, 0);
    cudaEventRecord(evG0, 0);

    // s3: tail half 0 (needs glu half 0 + folded weights) — overlaps glu half 1
    cudaStreamWaitEvent(s3, evG0, 0);
    cudaStreamWaitEvent(s3, evPre, 0);
    k_tail<<<256, 256, T3_SMEM, s3>>>(b1, x, out, 0);
    cudaEventRecord(evT0, s3);

    // main stream: glu half 1, then tail half 1
    k_glu<<<256, 256, GLU_SMEM>>>(x, lng, lnb, bd, dww, bg, dwb, 256);
    cudaStreamWaitEvent(0, evPre, 0);
    k_tail<<<256, 256, T3_SMEM>>>(b1, x, out, 256);
    cudaStreamWaitEvent(0, evT0, 0);   // join: both halves complete on main stream
}

// round 17
// speedup vs baseline: 1.0459x; 1.0459x over previous
#include <cuda_runtime.h>
#include <cuda_fp16.h>
#include <mma.h>
#include <cstdint>

using namespace nvcuda;

#define NB 32768
#define NC 1024
#define NCH 256
#define NR 16

// ---------------- device scratch ----------------
__device__ __half g_h1[(size_t)NB * NCH];
__device__ __half g_Wcat[NC * 2 * NCH];
__device__ __half g_W1b[NCH * NCH];
__device__ __half g_Wbig[NCH * NC];
__device__ float g_T1[NCH * NR];
__device__ float g_Wueff[NCH * NC];
__device__ float g_Wf1[NCH * NCH];
__device__ float g_Wf2[NCH * NCH];
__device__ float g_v2[NCH];
__device__ float g_bu1[NR];
__device__ float g_bueff[NC];
__device__ float g_bbig[NC];

// ---------------- cp.async helpers ----------------
__device__ __forceinline__ void cp16(void* s, const void* g) {
    unsigned int sa = (unsigned int)__cvta_generic_to_shared(s);
    asm volatile("cp.async.cg.shared.global [%0], [%1], 16;\n" :: "r"(sa), "l"(g));
}
__device__ __forceinline__ void cp_commit() { asm volatile("cp.async.commit_group;\n" ::: "memory"); }
template<int N>
__device__ __forceinline__ void cp_wait() { asm volatile("cp.async.wait_group %0;\n" :: "n"(N) : "memory"); }

// ---------------- fp32 fold GEMM tile (k-step 32), f32 or f16 output ----------------
template <typename OutT>
__device__ void gemm_tile32(const float* __restrict__ A, const float* __restrict__ B,
                            OutT* __restrict__ C, int N, int K, int m0, int n0,
                            int tid, char* sm) {
    float (*As)[33] = (float(*)[33])sm;
    float (*Bs)[64] = (float(*)[64])(sm + 64 * 33 * 4);
    int ty = tid >> 4, tx = tid & 15;
    float acc[4][4] = {};
    for (int k0 = 0; k0 < K; k0 += 32) {
        #pragma unroll
        for (int l = 0; l < 8; l++) {
            int idx = tid + l * 256;
            int r = idx >> 5, c = idx & 31;
            As[r][c] = A[(size_t)(m0 + r) * K + k0 + c];
        }
        #pragma unroll
        for (int l = 0; l < 8; l++) {
            int idx = tid + l * 256;
            int r = idx >> 6, c = idx & 63;
            Bs[r][c] = B[(size_t)(k0 + r) * N + n0 + c];
        }
        __syncthreads();
        #pragma unroll
        for (int k = 0; k < 32; k++) {
            float a[4], b[4];
            #pragma unroll
            for (int i = 0; i < 4; i++) a[i] = As[ty * 4 + i][k];
            #pragma unroll
            for (int j = 0; j < 4; j++) b[j] = Bs[k][tx * 4 + j];
            #pragma unroll
            for (int i = 0; i < 4; i++)
                #pragma unroll
                for (int j = 0; j < 4; j++) acc[i][j] += a[i] * b[j];
        }
        __syncthreads();
    }
    #pragma unroll
    for (int i = 0; i < 4; i++)
        #pragma unroll
        for (int j = 0; j < 4; j++)
            C[(size_t)(m0 + ty * 4 + i) * N + n0 + tx * 4 + j] = (OutT)acc[i][j];
}

// ---------------- prologue kernels (R15-proven) ----------------

__global__ void k_convWcat(const float* __restrict__ Wd, const float* __restrict__ dww,
                           const float* __restrict__ Wg) {
    int idx = blockIdx.x * 256 + threadIdx.x;
    int k = idx >> 9, j = idx & 511;
    float v = (j < NCH) ? Wd[k * NCH + j] * dww[j] : Wg[k * NCH + (j - NCH)];
    g_Wcat[idx] = __float2half(v);
}

__global__ void k_fold(const float* __restrict__ Wu, const float* __restrict__ Wld,
                       const float* __restrict__ bu, const float* __restrict__ W1) {
    int b = blockIdx.x, tid = threadIdx.x;
    if (b >= 257) {
        int idx = (b - 257) * 256 + tid;
        g_W1b[idx] = __float2half(W1[idx]);
        return;
    }
    int wid = tid >> 5, lane = tid & 31;
    if (b == 256) {
        if (tid < NR) {
            float s = 0.f;
            for (int c = 0; c < NC; c++) s += bu[c] * Wld[c * NR + tid];
            g_bu1[tid] = s;
        }
        return;
    }
    float acc[NR];
    #pragma unroll
    for (int r = 0; r < NR; r++) acc[r] = 0.f;
    for (int c = tid; c < NC; c += 256) {
        float w = Wu[b * NC + c];
        #pragma unroll
        for (int r = 0; r < NR; r++) acc[r] += w * Wld[c * NR + r];
    }
    #pragma unroll
    for (int r = 0; r < NR; r++)
        #pragma unroll
        for (int o = 16; o > 0; o >>= 1) acc[r] += __shfl_xor_sync(0xffffffffu, acc[r], o);
    __shared__ float s[8][NR];
    if (lane == 0)
        #pragma unroll
        for (int r = 0; r < NR; r++) s[wid][r] = acc[r];
    __syncthreads();
    if (tid < NR) {
        float v = 0.f;
        #pragma unroll
        for (int w = 0; w < 8; w++) v += s[w][tid];
        g_T1[b * NR + tid] = v;
    }
}

__global__ void k_pre1(const float* __restrict__ Wu, const float* __restrict__ Wlu,
                       const float* __restrict__ bu, const float* __restrict__ W2,
                       const float* __restrict__ Wv, const float* __restrict__ b2,
                       const float* __restrict__ bv, const float* __restrict__ Wo,
                       const float* __restrict__ bo) {
    __shared__ char sm[16896];
    int b = blockIdx.x, tid = threadIdx.x;
    if (b < 1024) {
        int idx = b * 256 + tid;
        int i = idx >> 10, c = idx & 1023;
        float s = Wu[idx];
        #pragma unroll
        for (int r = 0; r < NR; r++) s += g_T1[i * NR + r] * Wlu[r * NC + c];
        g_Wueff[idx] = s;
        return;
    }
    if (b < 1028) {
        int c = (b - 1024) * 256 + tid;
        float s = bu[c];
        #pragma unroll
        for (int r = 0; r < NR; r++) s += g_bu1[r] * Wlu[r * NC + c];
        g_bueff[c] = s;
        return;
    }
    if (b < 1044) {
        int t = b - 1028;
        gemm_tile32<float>(W2, Wv, g_Wf1, NCH, NCH, (t >> 2) * 64, (t & 3) * 64, tid, sm);
        return;
    }
    float* sv1 = (float*)sm;
    int n = tid;
    float s = bv[n];
    for (int k = 0; k < NCH; k++) s += b2[k] * Wv[k * NCH + n];
    sv1[n] = s;
    __syncthreads();
    float t = bo[n];
    for (int k = 0; k < NCH; k++) t += sv1[k] * Wo[k * NCH + n];
    g_v2[n] = t;
}

__global__ void k_pre2(const float* __restrict__ Wo) {
    __shared__ char sm[16896];
    int t = blockIdx.x;
    gemm_tile32<float>(g_Wf1, Wo, g_Wf2, NCH, NCH, (t >> 2) * 64, (t & 3) * 64, threadIdx.x, sm);
}

__global__ void k_pre3() {
    __shared__ char sm[16896];
    int b = blockIdx.x, tid = threadIdx.x;
    if (b < 64) {
        gemm_tile32<__half>(g_Wf2, g_Wueff, g_Wbig, NC, NCH, (b >> 4) * 64, (b & 15) * 64, tid, sm);
        return;
    }
    int n = (b - 64) * 256 + tid;
    float s = g_bueff[n];
    for (int k = 0; k < NCH; k++) s += g_v2[k] * g_Wueff[k * NC + n];
    g_bbig[n] = s;
}

// ---------------- fused LN + GLU GEMM (R14-proven, fp16) ----------------
#define GLU_SAS 1032
#define GLU_SBS 520
#define GLU_PS  520
#define GLU_ASZ (64 * GLU_SAS * 2)
#define GLU_BSZ (32 * GLU_SBS * 2)
#define GLU_SMEM (GLU_ASZ + 3 * GLU_BSZ)

__device__ __forceinline__ void glu_prefB(__half* sB, int k0, int tid) {
    #pragma unroll
    for (int j = 0; j < 8; j++) {
        int idx = tid + j * 256;
        int row = idx >> 6, c16 = idx & 63;
        cp16(sB + row * GLU_SBS + c16 * 8, g_Wcat + (size_t)(k0 + row) * 512 + c16 * 8);
    }
}

__global__ __launch_bounds__(256, 1)
void k_glu(const float* __restrict__ x, const float* __restrict__ lg,
           const float* __restrict__ lb, const float* __restrict__ bd,
           const float* __restrict__ dww, const float* __restrict__ bg,
           const float* __restrict__ dwb) {
    extern __shared__ char smem[];
    __half* sA = (__half*)smem;
    __half* sB[3] = {
        (__half*)(smem + GLU_ASZ),
        (__half*)(smem + GLU_ASZ + GLU_BSZ),
        (__half*)(smem + GLU_ASZ + 2 * GLU_BSZ)
    };
    __half* patch = (__half*)smem;

    const int tid = threadIdx.x, wid = tid >> 5, lane = tid & 31;
    const int m0 = blockIdx.x * 64;

    glu_prefB(sB[0], 0, tid);
    cp_commit();

    #pragma unroll
    for (int rr = 0; rr < 8; rr++) {
        int r = wid * 8 + rr;
        const float4* xr = (const float4*)(x + (size_t)(m0 + r) * NC);
        float4 v[8];
        float s = 0.f, q = 0.f;
        #pragma unroll
        for (int i = 0; i < 8; i++) {
            v[i] = xr[lane + i * 32];
            s += v[i].x + v[i].y + v[i].z + v[i].w;
            q = fmaf(v[i].x, v[i].x, q); q = fmaf(v[i].y, v[i].y, q);
            q = fmaf(v[i].z, v[i].z, q); q = fmaf(v[i].w, v[i].w, q);
        }
        #pragma unroll
        for (int o = 16; o > 0; o >>= 1) {
            s += __shfl_xor_sync(0xffffffffu, s, o);
            q += __shfl_xor_sync(0xffffffffu, q, o);
        }
        float mean = s * (1.f / NC);
        float rstd = rsqrtf(q * (1.f / NC) - mean * mean + 1e-5f);
        #pragma unroll
        for (int i = 0; i < 8; i++) {
            float4 g4 = ((const float4*)lg)[lane + i * 32];
            float4 b4 = ((const float4*)lb)[lane + i * 32];
            __align__(8) __half o4[4];
            o4[0] = __float2half((v[i].x - mean) * rstd * g4.x + b4.x);
            o4[1] = __float2half((v[i].y - mean) * rstd * g4.y + b4.y);
            o4[2] = __float2half((v[i].z - mean) * rstd * g4.z + b4.z);
            o4[3] = __float2half((v[i].w - mean) * rstd * g4.w + b4.w);
            *(uint2*)(sA + r * GLU_SAS + (lane + i * 32) * 4) = *(const uint2*)o4;
        }
    }
    glu_prefB(sB[1], 32, tid);
    cp_commit();
    cp_wait<1>();
    __syncthreads();

    const int wm = wid >> 2, wn = wid & 3;
    wmma::fragment<wmma::accumulator, 16, 16, 16, __half> acc[2][8];
    #pragma unroll
    for (int i = 0; i < 2; i++)
        #pragma unroll
        for (int j = 0; j < 8; j++) wmma::fill_fragment(acc[i][j], __float2half(0.f));

    for (int it = 0; it < 32; it++) {
        int k0 = it * 32;
        if (it + 2 < 32) { glu_prefB(sB[(it + 2) % 3], k0 + 64, tid); cp_commit(); }
        __half* sBc = sB[it % 3];
        #pragma unroll
        for (int kk = 0; kk < 32; kk += 16) {
            wmma::fragment<wmma::matrix_a, 16, 16, 16, __half, wmma::row_major> af[2];
            #pragma unroll
            for (int i = 0; i < 2; i++)
                wmma::load_matrix_sync(af[i], sA + (wm * 32 + i * 16) * GLU_SAS + k0 + kk, GLU_SAS);
            #pragma unroll
            for (int gset = 0; gset < 2; gset++) {
                wmma::fragment<wmma::matrix_b, 16, 16, 16, __half, wmma::row_major> bf[4];
                #pragma unroll
                for (int j = 0; j < 4; j++)
                    wmma::load_matrix_sync(bf[j], sBc + kk * GLU_SBS + wn * 128 + gset * 64 + j * 16, GLU_SBS);
                #pragma unroll
                for (int i = 0; i < 2; i++)
                    #pragma unroll
                    for (int j = 0; j < 4; j++)
                        wmma::mma_sync(acc[i][gset * 4 + j], af[i], bf[j], acc[i][gset * 4 + j]);
            }
        }
        if (it < 31) {
            if (it < 30) cp_wait<1>();
            else         cp_wait<0>();
            __syncthreads();
        }
    }
    __syncthreads();

    #pragma unroll
    for (int i = 0; i < 2; i++)
        #pragma unroll
        for (int j = 0; j < 8; j++)
            wmma::store_matrix_sync(patch + (size_t)(wm * 32 + i * 16) * GLU_PS + wn * 128 + j * 16,
                                    acc[i][j], GLU_PS, wmma::mem_row_major);
    __syncthreads();

    const int r = tid >> 2;
    const int cb = (tid & 3) * 64;
    #pragma unroll
    for (int c8 = 0; c8 < 64; c8 += 8) {
        __align__(16) __half tmp[8];
        #pragma unroll
        for (int t = 0; t < 8; t++) {
            int j = cb + c8 + t;
            float a = __half2float(patch[r * GLU_PS + j]) + bd[j] * dww[j];
            float g = __half2float(patch[r * GLU_PS + 256 + j]) + bg[j];
            float sg = 1.f / (1.f + __expf(-g));
            tmp[t] = __float2half(a * sg + dwb[j]);
        }
        *(uint4*)(g_h1 + (size_t)(m0 + r) * NCH + cb + c8) = *(const uint4*)tmp;
    }
}

// ---------------- k_tail v5: M=128 per CTA, grid 256 ----------------
// smem (167424 B):
//   sU   [0, 67584)          128 x 264 half (h1, then u)
//   ring [67584, 167424)     3 x 33280 (W chunks; the just-consumed slot doubles
//                            as the epilogue patch — slot-disjoint from in-flight
//                            prefetches by the t%3 rotation)
// chunks t=0..7  GEMM1: W1 k0=t*32 (32 x 256, stride 264)
//        t=8..23 GEMM2: np=(t-8)>>3, k0=((t-8)&7)*32 (32 x 512, stride 520)
#define T5_HS 264
#define T5_W1S 264
#define T5_W2S 520
#define T5_P1S 260
#define T5_P2S 516
#define T5_OFF_RING 67584
#define T5_BUF 33280
#define T5_SMEM 167424

__device__ __forceinline__ float gelu_tanh(float v) {
    return 0.5f * v * (1.f + tanhf(0.7978845608028654f * (v + 0.044715f * v * v * v)));
}

__device__ __forceinline__ void t5_prefW(char* smem, int t, int tid) {
    __half* dst = (__half*)(smem + T5_OFF_RING + (t % 3) * T5_BUF);
    if (t < 8) {
        int k0 = t * 32;
        #pragma unroll
        for (int j = 0; j < 4; j++) {
            int idx = tid + j * 256;
            int row = idx >> 5, c16 = idx & 31;      // 32 x 256
            cp16(dst + row * T5_W1S + c16 * 8, g_W1b + (size_t)(k0 + row) * NCH + c16 * 8);
        }
    } else {
        int np = (t - 8) >> 3, k0 = ((t - 8) & 7) * 32;
        #pragma unroll
        for (int j = 0; j < 8; j++) {
            int idx = tid + j * 256;
            int row = idx >> 6, c16 = idx & 63;      // 32 x 512
            cp16(dst + row * T5_W2S + c16 * 8, g_Wbig + (size_t)(k0 + row) * NC + np * 512 + c16 * 8);
        }
    }
}

__global__ __launch_bounds__(256, 1)
void k_tail(const float* __restrict__ b1, const float* __restrict__ x,
            float* __restrict__ out) {
    extern __shared__ char smem[];
    __half* sU = (__half*)smem;

    const int tid = threadIdx.x, wid = tid >> 5;
    const int wm = wid >> 2, wn = wid & 3;       // wm: 64-row block, wn: col block
    const int m0 = blockIdx.x * 128;

    // h1 tile 128 x 256 = 4096 chunks -> 16 iters
    #pragma unroll
    for (int j = 0; j < 16; j++) {
        int idx = tid + j * 256;
        int row = idx >> 5, c16 = idx & 31;
        cp16(sU + row * T5_HS + c16 * 8, g_h1 + (size_t)(m0 + row) * NCH + c16 * 8);
    }
    cp_commit();
    t5_prefW(smem, 0, tid); cp_commit();
    t5_prefW(smem, 1, tid); cp_commit();

    wmma::fragment<wmma::accumulator, 16, 16, 16, __half> acc[4][8];
    #pragma unroll
    for (int i = 0; i < 4; i++)
        #pragma unroll
        for (int j = 0; j < 8; j++) wmma::fill_fragment(acc[i][j], __float2half(0.f));

    for (int t = 0; t < 24; t++) {
        if (t < 23) cp_wait<1>(); else cp_wait<0>();
        __syncthreads();
        __half* sW = (__half*)(smem + T5_OFF_RING + (t % 3) * T5_BUF);

        if (t < 8) {
            // GEMM1 chunk: warp tile 64x64 (acc[0..3][0..3])
            int k0 = t * 32;
            #pragma unroll
            for (int kk = 0; kk < 32; kk += 16) {
                wmma::fragment<wmma::matrix_a, 16, 16, 16, __half, wmma::row_major> af[4];
                wmma::fragment<wmma::matrix_b, 16, 16, 16, __half, wmma::row_major> bf[4];
                #pragma unroll
                for (int i = 0; i < 4; i++)
                    wmma::load_matrix_sync(af[i], sU + (wm * 64 + i * 16) * T5_HS + k0 + kk, T5_HS);
                #pragma unroll
                for (int j = 0; j < 4; j++)
                    wmma::load_matrix_sync(bf[j], sW + kk * T5_W1S + wn * 64 + j * 16, T5_W1S);
                #pragma unroll
                for (int i = 0; i < 4; i++)
                    #pragma unroll
                    for (int j = 0; j < 4; j++)
                        wmma::mma_sync(acc[i][j], af[i], bf[j], acc[i][j]);
            }
        } else {
            // GEMM2 chunk: warp tile 64x128 over 512 cols (acc[0..3][0..7])
            int k0 = ((t - 8) & 7) * 32;
            #pragma unroll
            for (int kk = 0; kk < 32; kk += 16) {
                wmma::fragment<wmma::matrix_a, 16, 16, 16, __half, wmma::row_major> af[4];
                #pragma unroll
                for (int i = 0; i < 4; i++)
                    wmma::load_matrix_sync(af[i], sU + (wm * 64 + i * 16) * T5_HS + k0 + kk, T5_HS);
                #pragma unroll
                for (int gset = 0; gset < 2; gset++) {
                    wmma::fragment<wmma::matrix_b, 16, 16, 16, __half, wmma::row_major> bf[4];
                    #pragma unroll
                    for (int j = 0; j < 4; j++)
                        wmma::load_matrix_sync(bf[j], sW + kk * T5_W2S + wn * 128 + gset * 64 + j * 16, T5_W2S);
                    #pragma unroll
                    for (int i = 0; i < 4; i++)
                        #pragma unroll
                        for (int j = 0; j < 4; j++)
                            wmma::mma_sync(acc[i][gset * 4 + j], af[i], bf[j], acc[i][gset * 4 + j]);
                }
            }
        }
        __syncthreads();                         // reads of slot t%3 done
        if (t + 2 < 24) { t5_prefW(smem, t + 2, tid); cp_commit(); }

        if (t == 7) {
            // GEMM1 epilogue: u = gelu(acc + b1) -> sU (h1 fully consumed).
            // Patch = just-consumed ring slot (t%3); 4 quarter-passes of 32 rows.
            __half* patch = (__half*)(smem + T5_OFF_RING + (t % 3) * T5_BUF);
            #pragma unroll
            for (int q = 0; q < 4; q++) {
                if (wm == (q >> 1)) {
                    int ib = (q & 1) * 2;
                    #pragma unroll
                    for (int ii = 0; ii < 2; ii++)
                        #pragma unroll
                        for (int j = 0; j < 4; j++)
                            wmma::store_matrix_sync(patch + (size_t)(ii * 16) * T5_P1S + wn * 64 + j * 16,
                                                    acc[ib + ii][j], T5_P1S, wmma::mem_row_major);
                }
                __syncthreads();
                const int r2 = tid >> 3, cb = (tid & 7) * 32;
                #pragma unroll
                for (int c8 = 0; c8 < 32; c8 += 8) {
                    __align__(16) __half tmp[8];
                    #pragma unroll
                    for (int u = 0; u < 8; u++) {
                        int j = cb + c8 + u;
                        tmp[u] = __float2half(gelu_tanh(__half2float(patch[r2 * T5_P1S + j]) + b1[j]));
                    }
                    *(uint4*)(sU + (q * 32 + r2) * T5_HS + cb + c8) = *(const uint4*)tmp;
                }
                __syncthreads();
            }
            #pragma unroll
            for (int i = 0; i < 4; i++)
                #pragma unroll
                for (int j = 0; j < 8; j++) wmma::fill_fragment(acc[i][j], __float2half(0.f));
        } else if (t == 15 || t == 23) {
            // GEMM2 pass epilogue: 512 out cols, 4 quarter-passes of 32 rows.
            int np = (t - 8) >> 3;
            __half* patch = (__half*)(smem + T5_OFF_RING + (t % 3) * T5_BUF);
            #pragma unroll
            for (int q = 0; q < 4; q++) {
                if (wm == (q >> 1)) {
                    int ib = (q & 1) * 2;
                    #pragma unroll
                    for (int ii = 0; ii < 2; ii++)
                        #pragma unroll
                        for (int j = 0; j < 8; j++)
                            wmma::store_matrix_sync(patch + (size_t)(ii * 16) * T5_P2S + wn * 128 + j * 16,
                                                    acc[ib + ii][j], T5_P2S, wmma::mem_row_major);
                }
                __syncthreads();
                const int r2 = tid >> 3, cb = (tid & 7) * 64;
                const int gr = m0 + q * 32 + r2;
                #pragma unroll
                for (int c4 = 0; c4 < 64; c4 += 4) {
                    int j = cb + c4;
                    int gc = np * 512 + j;
                    float4 xo = *(const float4*)(x + (size_t)gr * NC + gc);
                    float4 o;
                    o.x = 0.5f * (__half2float(patch[r2 * T5_P2S + j + 0]) + g_bbig[gc + 0]) + 0.5f * xo.x;
                    o.y = 0.5f * (__half2float(patch[r2 * T5_P2S + j + 1]) + g_bbig[gc + 1]) + 0.5f * xo.y;
                    o.z = 0.5f * (__half2float(patch[r2 * T5_P2S + j + 2]) + g_bbig[gc + 2]) + 0.5f * xo.z;
                    o.w = 0.5f * (__half2float(patch[r2 * T5_P2S + j + 3]) + g_bbig[gc + 3]) + 0.5f * xo.w;
                    *(float4*)(out + (size_t)gr * NC + gc) = o;
                }
                __syncthreads();
            }
            if (t == 15) {
                #pragma unroll
                for (int i = 0; i < 4; i++)
                    #pragma unroll
                    for (int j = 0; j < 8; j++) wmma::fill_fragment(acc[i][j], __float2half(0.f));
            }
        }
    }
}

// ---------------- host launch: 2-stream fork/join (R15-proven) ----------------
extern "C" void kernel_launch(void* const* d_in, const int* in_sizes, int n_in,
                              void* d_out, int out_size) {
    const float* x   = (const float*)d_in[0];
    const float* lng = (const float*)d_in[1];
    const float* lnb = (const float*)d_in[2];
    const float* Wd  = (const float*)d_in[3];
    const float* bd  = (const float*)d_in[4];
    const float* Wg  = (const float*)d_in[5];
    const float* bg  = (const float*)d_in[6];
    const float* dww = (const float*)d_in[7];
    const float* dwb = (const float*)d_in[8];
    const float* W1  = (const float*)d_in[9];
    const float* b1  = (const float*)d_in[10];
    const float* W2  = (const float*)d_in[11];
    const float* b2  = (const float*)d_in[12];
    // d_in[13..16] dead (softmax over one key == 1)
    const float* Wv  = (const float*)d_in[17];
    const float* bv  = (const float*)d_in[18];
    const float* Wo  = (const float*)d_in[19];
    const float* bo  = (const float*)d_in[20];
    const float* Wu  = (const float*)d_in[21];
    const float* bu  = (const float*)d_in[22];
    const float* Wld = (const float*)d_in[23];
    const float* Wlu = (const float*)d_in[24];
    float* out = (float*)d_out;

    static int inited = 0;
    static cudaStream_t s2;
    static cudaEvent_t evStart, evPre;
    if (!inited) {
        cudaFuncSetAttribute(k_glu,  cudaFuncAttributeMaxDynamicSharedMemorySize, GLU_SMEM);
        cudaFuncSetAttribute(k_tail, cudaFuncAttributeMaxDynamicSharedMemorySize, T5_SMEM);
        cudaStreamCreateWithFlags(&s2, cudaStreamNonBlocking);
        cudaEventCreateWithFlags(&evStart, cudaEventDisableTiming);
        cudaEventCreateWithFlags(&evPre, cudaEventDisableTiming);
        inited = 1;
    }

    cudaEventRecord(evStart, 0);
    cudaStreamWaitEvent(s2, evStart, 0);

    // main stream: k_glu dependency chain
    k_convWcat<<<2048, 256>>>(Wd, dww, Wg);
    k_glu<<<512, 256, GLU_SMEM>>>(x, lng, lnb, bd, dww, bg, dwb);

    // side stream: weight folding chain (hidden under k_glu)
    k_fold<<<513, 256, 0, s2>>>(Wu, Wld, bu, W1);
    k_pre1<<<1045, 256, 0, s2>>>(Wu, Wlu, bu, W2, Wv, b2, bv, Wo, bo);
    k_pre2<<<16, 256, 0, s2>>>(Wo);
    k_pre3<<<68, 256, 0, s2>>>();
    cudaEventRecord(evPre, s2);

    // join: tail needs g_h1 (main) + folded weights (s2)
    cudaStreamWaitEvent(0, evPre, 0);
    k_tail<<<256, 256, T5_SMEM>>>(b1, x, out);
}